// round 1
// baseline (speedup 1.0000x reference)
#include <cuda_runtime.h>
#include <math.h>

#define NN 50000
#define FF 64
#define HH 32
#define TT 8
#define EE 800000
#define PP 800000

// ---------------- scratch (device globals; no allocation allowed) ----------
__device__ float g_deg[NN];
__device__ float g_norm[EE];
__device__ float g_H[NN * HH];
__device__ float g_C[NN * HH];
__device__ float g_TX1[NN * FF];
__device__ float g_TH1[NN * HH];
__device__ float g_P2X[NN * FF];
__device__ float g_P2H[NN * HH];
__device__ float g_C0[NN * 128];
__device__ float g_Wall[224 * 128];
__device__ float g_WC0[FF * 128];
__device__ float g_bias[128];
__device__ float g_h1[NN * 16];

__device__ __forceinline__ void red4(float* p, float4 v) {
    asm volatile("red.global.add.v4.f32 [%0], {%1,%2,%3,%4};"
                 :: "l"(p), "f"(v.x), "f"(v.y), "f"(v.z), "f"(v.w)
                 : "memory");
}

__device__ __forceinline__ float sigmoidf_(float x) {
    return 1.f / (1.f + expf(-x));
}

// ---------------- weight prep: fold gates + cheb identity -------------------
// Wall[k][o], o = g*32+h:
//  k[0,64)   : WX1            (multiplies TX1 = L x)
//  k[64,128) : 2*WX2          (multiplies P2X = L TX1)
//  k[128,160): WH0 - WH2      (multiplies H)
//  k[160,192): WH1            (multiplies TH1 = L H)
//  k[192,224): 2*WH2          (multiplies P2H = L TH1)
// WC0[f][o] = WX0 - WX2  (multiplies x, folded into C0)
// bias[o]   = bx + bh + b_gate
__global__ void prep_weights(const float* __restrict__ Wx, const float* __restrict__ bx,
                             const float* __restrict__ Wh, const float* __restrict__ bh,
                             const float* __restrict__ bg) {
    int i = blockIdx.x * blockDim.x + threadIdx.x;
    const int total = 224 * 128 + 64 * 128 + 128;
    for (; i < total; i += gridDim.x * blockDim.x) {
        if (i < 224 * 128) {
            int k = i >> 7, o = i & 127;
            int g = o >> 5, h = o & 31;
            float v;
            if (k < 64)       v = Wx[((g * 3 + 1) * 64 + k) * 32 + h];
            else if (k < 128) v = 2.f * Wx[((g * 3 + 2) * 64 + (k - 64)) * 32 + h];
            else if (k < 160) v = Wh[((g * 3 + 0) * 32 + (k - 128)) * 32 + h]
                                - Wh[((g * 3 + 2) * 32 + (k - 128)) * 32 + h];
            else if (k < 192) v = Wh[((g * 3 + 1) * 32 + (k - 160)) * 32 + h];
            else              v = 2.f * Wh[((g * 3 + 2) * 32 + (k - 192)) * 32 + h];
            g_Wall[i] = v;
        } else if (i < 224 * 128 + 64 * 128) {
            int j = i - 224 * 128;
            int f = j >> 7, o = j & 127;
            int g = o >> 5, h = o & 31;
            g_WC0[j] = Wx[((g * 3 + 0) * 64 + f) * 32 + h]
                     - Wx[((g * 3 + 2) * 64 + f) * 32 + h];
        } else {
            int o = i - 224 * 128 - 64 * 128;
            int g = o >> 5, h = o & 31;
            g_bias[o] = bx[g * 32 + h] + bh[g * 32 + h] + bg[g * 32 + h];
        }
    }
}

// ---------------- C0 = x @ WC0 + bias (once per launch) ---------------------
__global__ void c0_kernel(const float* __restrict__ x) {
    __shared__ float sW[64 * 128];
    __shared__ float sx[16 * 64];
    int tid = threadIdx.x;                       // 128 threads
    for (int i = tid; i < 64 * 128; i += 128) sW[i] = g_WC0[i];
    int nb = blockIdx.x * 16;
    for (int i = tid; i < 16 * 64; i += 128) {
        int nl = i >> 6, f = i & 63;
        int n = nb + nl;
        sx[i] = (n < NN) ? x[n * 64 + f] : 0.f;
    }
    __syncthreads();
    float b = g_bias[tid];
    for (int j = 0; j < 16; j++) {
        int n = nb + j;
        if (n >= NN) break;
        float acc = b;
#pragma unroll 8
        for (int f = 0; f < 64; f++) acc += sx[j * 64 + f] * sW[f * 128 + tid];
        g_C0[n * 128 + tid] = acc;
    }
}

// ---------------- state / scratch zeroing -----------------------------------
__global__ void zero_state() {
    int i = blockIdx.x * blockDim.x + threadIdx.x;
    int stride = gridDim.x * blockDim.x;
    for (int j = i; j < NN * HH; j += stride) { g_H[j] = 0.f; g_C[j] = 0.f; }
}

__global__ void zero_step() {
    int i = blockIdx.x * blockDim.x + threadIdx.x;
    int stride = gridDim.x * blockDim.x;
    for (int j = i; j < NN; j += stride) g_deg[j] = 0.f;
    for (int j = i; j < NN * FF; j += stride) { g_TX1[j] = 0.f; g_P2X[j] = 0.f; }
    for (int j = i; j < NN * HH; j += stride) { g_TH1[j] = 0.f; g_P2H[j] = 0.f; }
}

// ---------------- degree + norm ---------------------------------------------
__global__ void deg_kernel(const int* __restrict__ rows) {
    int e = blockIdx.x * blockDim.x + threadIdx.x;
    if (e < EE) atomicAdd(&g_deg[rows[e]], 1.0f);
}

__global__ void norm_kernel(const int* __restrict__ rows, const int* __restrict__ cols) {
    int e = blockIdx.x * blockDim.x + threadIdx.x;
    if (e < EE) {
        float dr = g_deg[rows[e]], dc = g_deg[cols[e]];
        float a = dr > 0.f ? rsqrtf(dr) : 0.f;
        float b = dc > 0.f ? rsqrtf(dc) : 0.f;
        g_norm[e] = -a * b;
    }
}

// ---------------- Laplacian propagation (x 64 feats + H 32 feats fused) -----
// pass 0: TX1 += L x, TH1 += L H       (inputs X, g_H)
// pass 1: P2X += L TX1, P2H += L TH1
// thread = (edge, float4-chunk); 24 chunks per edge (16 x-chunks, 8 h-chunks)
__global__ void prop_kernel(const int* __restrict__ rows, const int* __restrict__ cols,
                            const float* __restrict__ X, int pass) {
    unsigned gid = blockIdx.x * blockDim.x + threadIdx.x;
    if (gid >= (unsigned)(EE) * 24u) return;
    unsigned e = gid / 24u;
    unsigned c = gid - e * 24u;
    float w = g_norm[e];
    if (w == 0.f) return;
    int r = rows[e], cl = cols[e];
    const float* xin = pass ? g_TX1 : X;
    const float* hin = pass ? g_TH1 : g_H;
    float* xout = pass ? g_P2X : g_TX1;
    float* hout = pass ? g_P2H : g_TH1;
    if (c < 16u) {
        float4 v = *(const float4*)(xin + (size_t)r * 64 + c * 4);
        float4 u = make_float4(v.x * w, v.y * w, v.z * w, v.w * w);
        red4(xout + (size_t)cl * 64 + c * 4, u);
    } else {
        unsigned c2 = c - 16u;
        float4 v = *(const float4*)(hin + (size_t)r * 32 + c2 * 4);
        float4 u = make_float4(v.x * w, v.y * w, v.z * w, v.w * w);
        red4(hout + (size_t)cl * 32 + c2 * 4, u);
    }
}

// ---------------- fused gate matmul + LSTM update ---------------------------
// GATES[n][128] = C0[n] + [TX1|P2X|H|TH1|P2H][n] @ Wall, then in-register LSTM.
// block: 64 nodes x 128 outs, 256 threads: nt=tid&7 (8 node groups x 8 nodes),
// ot=tid>>3 (32 channels; each thread owns all 4 gates of its channel).
__global__ void gates_kernel(const float* __restrict__ wc) {
    __shared__ float sIn[32 * 65];
    __shared__ float sW[32 * 128];
    int tid = threadIdx.x;
    int nt = tid & 7, ot = tid >> 3;
    int nb = blockIdx.x * 64;
    float acc[8][4];
#pragma unroll
    for (int j = 0; j < 8; j++) {
        int n = nb + nt + 8 * j;
#pragma unroll
        for (int g = 0; g < 4; g++)
            acc[j][g] = (n < NN) ? g_C0[(size_t)n * 128 + ot + 32 * g] : 0.f;
    }
    for (int cc = 0; cc < 7; cc++) {
        const float* src; int stride, off;
        if (cc < 2)       { src = g_TX1; stride = 64; off = cc * 32; }
        else if (cc < 4)  { src = g_P2X; stride = 64; off = (cc - 2) * 32; }
        else if (cc == 4) { src = g_H;   stride = 32; off = 0; }
        else if (cc == 5) { src = g_TH1; stride = 32; off = 0; }
        else              { src = g_P2H; stride = 32; off = 0; }
#pragma unroll
        for (int i = 0; i < 8; i++) {
            int lin = i * 256 + tid;
            int kk = lin & 31, nl = lin >> 5;
            int n = nb + nl;
            sIn[kk * 65 + nl] = (n < NN) ? src[(size_t)n * stride + off + kk] : 0.f;
        }
        int k0 = cc * 32;
#pragma unroll
        for (int i = 0; i < 16; i++) {
            int lin = i * 256 + tid;
            sW[lin] = g_Wall[k0 * 128 + lin];
        }
        __syncthreads();
#pragma unroll 4
        for (int kk = 0; kk < 32; kk++) {
            float a[8];
#pragma unroll
            for (int j = 0; j < 8; j++) a[j] = sIn[kk * 65 + nt + 8 * j];
            float w0 = sW[kk * 128 + ot];
            float w1 = sW[kk * 128 + 32 + ot];
            float w2 = sW[kk * 128 + 64 + ot];
            float w3 = sW[kk * 128 + 96 + ot];
#pragma unroll
            for (int j = 0; j < 8; j++) {
                acc[j][0] += a[j] * w0;
                acc[j][1] += a[j] * w1;
                acc[j][2] += a[j] * w2;
                acc[j][3] += a[j] * w3;
            }
        }
        __syncthreads();
    }
    float wci = wc[ot], wcf = wc[32 + ot], wco = wc[64 + ot];
#pragma unroll
    for (int j = 0; j < 8; j++) {
        int n = nb + nt + 8 * j;
        if (n < NN) {
            float cs = g_C[(size_t)n * 32 + ot];
            float ig = sigmoidf_(acc[j][0] + wci * cs);
            float fg = sigmoidf_(acc[j][1] + wcf * cs);
            float gt = tanhf(acc[j][2]);
            float cn = fg * cs + ig * gt;
            float og = sigmoidf_(acc[j][3] + wco * cn);
            g_C[(size_t)n * 32 + ot] = cn;
            g_H[(size_t)n * 32 + ot] = og * tanhf(cn);
        }
    }
}

// ---------------- head: h1 = relu(relu(H) @ fc1 + b1) -----------------------
__global__ void h1_kernel(const float* __restrict__ w, const float* __restrict__ b) {
    __shared__ float sw[32 * 16];
    __shared__ float sb[16];
    int tid = threadIdx.x;
    for (int i = tid; i < 512; i += blockDim.x) sw[i] = w[i];
    if (tid < 16) sb[tid] = b[tid];
    __syncthreads();
    int n = blockIdx.x * blockDim.x + tid;
    if (n >= NN) return;
    float h[32];
#pragma unroll
    for (int k = 0; k < 32; k++) h[k] = fmaxf(g_H[(size_t)n * 32 + k], 0.f);
#pragma unroll
    for (int o = 0; o < 16; o++) {
        float acc = sb[o];
#pragma unroll
        for (int k = 0; k < 32; k++) acc += h[k] * sw[k * 16 + o];
        g_h1[(size_t)n * 16 + o] = fmaxf(acc, 0.f);
    }
}

// ---------------- head: pair MLP --------------------------------------------
__global__ void pair_kernel(const int* __restrict__ src, const int* __restrict__ dst,
                            const float* __restrict__ w2, const float* __restrict__ b2,
                            const float* __restrict__ w3, const float* __restrict__ b3,
                            const float* __restrict__ wb, const float* __restrict__ bb,
                            float* __restrict__ out) {
    __shared__ float s2[512], s3[128], sb2[16], sb3[8], swb[8];
    __shared__ float sbb;
    int tid = threadIdx.x;
    for (int i = tid; i < 512; i += 256) s2[i] = w2[i];
    for (int i = tid; i < 128; i += 256) s3[i] = w3[i];
    if (tid < 16) sb2[tid] = b2[tid];
    if (tid < 8) { sb3[tid] = b3[tid]; swb[tid] = wb[tid]; }
    if (tid == 0) sbb = bb[0];
    __syncthreads();
    int p = blockIdx.x * 256 + tid;
    if (p >= PP) return;
    int s = src[p], d = dst[p];
    float z[32];
    const float4* hs = (const float4*)(g_h1 + (size_t)s * 16);
    const float4* hd = (const float4*)(g_h1 + (size_t)d * 16);
#pragma unroll
    for (int q = 0; q < 4; q++) {
        float4 v = hs[q];
        z[q * 4 + 0] = v.x; z[q * 4 + 1] = v.y; z[q * 4 + 2] = v.z; z[q * 4 + 3] = v.w;
    }
#pragma unroll
    for (int q = 0; q < 4; q++) {
        float4 v = hd[q];
        z[16 + q * 4 + 0] = v.x; z[16 + q * 4 + 1] = v.y; z[16 + q * 4 + 2] = v.z; z[16 + q * 4 + 3] = v.w;
    }
    float h2[16];
#pragma unroll
    for (int o = 0; o < 16; o++) {
        float acc = sb2[o];
#pragma unroll
        for (int k = 0; k < 32; k++) acc += z[k] * s2[k * 16 + o];
        h2[o] = fmaxf(acc, 0.f);
    }
    float h3[8];
#pragma unroll
    for (int o = 0; o < 8; o++) {
        float acc = sb3[o];
#pragma unroll
        for (int k = 0; k < 16; k++) acc += h2[k] * s3[k * 8 + o];
        h3[o] = fmaxf(acc, 0.f);
    }
    float acc = sbb;
#pragma unroll
    for (int k = 0; k < 8; k++) acc += h3[k] * swb[k];
    out[p] = sigmoidf_(acc);
}

// ---------------- launch ----------------------------------------------------
extern "C" void kernel_launch(void* const* d_in, const int* in_sizes, int n_in,
                              void* d_out, int out_size) {
    const float* x    = (const float*)d_in[0];
    const int*   ei   = (const int*)d_in[1];
    const int*   src  = (const int*)d_in[2];
    const int*   dst  = (const int*)d_in[3];
    const float* Wx   = (const float*)d_in[4];
    const float* bx   = (const float*)d_in[5];
    const float* Wh   = (const float*)d_in[6];
    const float* bh   = (const float*)d_in[7];
    const float* bg   = (const float*)d_in[8];
    const float* wc   = (const float*)d_in[9];
    const float* fc1w = (const float*)d_in[10];
    const float* fc1b = (const float*)d_in[11];
    const float* fc2w = (const float*)d_in[12];
    const float* fc2b = (const float*)d_in[13];
    const float* fc3w = (const float*)d_in[14];
    const float* fc3b = (const float*)d_in[15];
    const float* bfcw = (const float*)d_in[16];
    const float* bfcb = (const float*)d_in[17];
    float* out = (float*)d_out;

    prep_weights<<<64, 256>>>(Wx, bx, Wh, bh, bg);
    c0_kernel<<<(NN + 15) / 16, 128>>>(x);
    zero_state<<<512, 256>>>();

    for (int t = 0; t < TT; t++) {
        const int* rows = ei + (size_t)t * 2 * EE;
        const int* cols = rows + EE;
        zero_step<<<2048, 256>>>();
        deg_kernel<<<(EE + 255) / 256, 256>>>(rows);
        norm_kernel<<<(EE + 255) / 256, 256>>>(rows, cols);
        prop_kernel<<<(EE * 24 + 255) / 256, 256>>>(rows, cols, x, 0);
        prop_kernel<<<(EE * 24 + 255) / 256, 256>>>(rows, cols, x, 1);
        gates_kernel<<<(NN + 63) / 64, 256>>>(wc);
    }

    h1_kernel<<<(NN + 255) / 256, 256>>>(fc1w, fc1b);
    pair_kernel<<<(PP + 255) / 256, 256>>>(src, dst, fc2w, fc2b, fc3w, fc3b, bfcw, bfcb, out);
}

// round 4
// speedup vs baseline: 1.4831x; 1.4831x over previous
#include <cuda_runtime.h>
#include <math.h>

#define NN 50000
#define FF 64
#define HH 32
#define TT 8
#define EE 800000
#define PP 800000
#define SBLKS 196   // ceil(NN/256)

// ---------------- scratch (device globals; ~72 MB total) --------------------
__device__ int   g_deg[NN];          // out-degree (by row) for norm
__device__ int   g_cnt[NN];          // in-degree (by col) for CSR
__device__ float g_dis[NN];          // rsqrt(deg) or 0
__device__ int   g_bsum[256];
__device__ int   g_bpre[256];
__device__ int   g_startA[NN];
__device__ int   g_cursor[NN];
__device__ int   g_csr_src[EE];

__device__ float g_IN0[NN * 96];     // [x (64) | H (32)]
__device__ float g_OUT1[NN * 96];    // L * IN0
__device__ float g_OUT2[NN * 96];    // L * OUT1
__device__ float g_C[NN * HH];
__device__ float g_Wcat[288 * 128];  // unified gate weights
__device__ float g_bias[128];
__device__ float g_h1[NN * 16];

__device__ __forceinline__ float sigmoidf_(float x) {
    return 1.f / (1.f + expf(-x));
}

// ---------------- weight prep: unified K=288 weight + bias ------------------
// Wcat rows (k), outputs o = g*32+h:
//  [0,64)    : Wx0 - Wx2     (x part of IN0)
//  [64,96)   : Wh0 - Wh2     (H part of IN0)
//  [96,160)  : Wx1           (x part of OUT1 = L x)
//  [160,192) : Wh1           (H part of OUT1 = L H)
//  [192,256) : 2*Wx2         (x part of OUT2 = L^2 x)
//  [256,288) : 2*Wh2         (H part of OUT2 = L^2 H)
__global__ __launch_bounds__(256) void prep_weights(
        const float* __restrict__ Wx, const float* __restrict__ bx,
        const float* __restrict__ Wh, const float* __restrict__ bh,
        const float* __restrict__ bg) {
    int i = blockIdx.x * blockDim.x + threadIdx.x;
    const int total = 288 * 128 + 128;
    for (; i < total; i += gridDim.x * blockDim.x) {
        if (i < 288 * 128) {
            int k = i >> 7, o = i & 127;
            int g = o >> 5, h = o & 31;
            float v;
            if (k < 64)       v = Wx[((g * 3 + 0) * 64 + k) * 32 + h]
                                - Wx[((g * 3 + 2) * 64 + k) * 32 + h];
            else if (k < 96)  v = Wh[((g * 3 + 0) * 32 + (k - 64)) * 32 + h]
                                - Wh[((g * 3 + 2) * 32 + (k - 64)) * 32 + h];
            else if (k < 160) v = Wx[((g * 3 + 1) * 64 + (k - 96)) * 32 + h];
            else if (k < 192) v = Wh[((g * 3 + 1) * 32 + (k - 160)) * 32 + h];
            else if (k < 256) v = 2.f * Wx[((g * 3 + 2) * 64 + (k - 192)) * 32 + h];
            else              v = 2.f * Wh[((g * 3 + 2) * 32 + (k - 256)) * 32 + h];
            g_Wcat[i] = v;
        } else {
            int o = i - 288 * 128;
            int g = o >> 5, h = o & 31;
            g_bias[o] = bx[g * 32 + h] + bh[g * 32 + h] + bg[g * 32 + h];
        }
    }
}

// ---------------- init: copy x into IN0, zero H part + C --------------------
__global__ __launch_bounds__(256) void copyx_kernel(const float* __restrict__ x) {
    int i = blockIdx.x * blockDim.x + threadIdx.x;
    int stride = gridDim.x * blockDim.x;
    for (int j = i; j < NN * 16; j += stride) {
        int n = j >> 4, c = j & 15;
        ((float4*)(g_IN0 + (size_t)n * 96))[c] = ((const float4*)x)[j];
    }
}

__global__ __launch_bounds__(256) void zero_state() {
    int i = blockIdx.x * blockDim.x + threadIdx.x;
    int stride = gridDim.x * blockDim.x;
    for (int j = i; j < NN * 8; j += stride) {
        int n = j >> 3, c = j & 7;
        float4 z = make_float4(0.f, 0.f, 0.f, 0.f);
        ((float4*)(g_IN0 + (size_t)n * 96 + 64))[c] = z;
        ((float4*)(g_C + (size_t)n * 32))[c] = z;
    }
}

__global__ __launch_bounds__(256) void zero_counts() {
    int i = blockIdx.x * blockDim.x + threadIdx.x;
    if (i < NN) { g_deg[i] = 0; g_cnt[i] = 0; }
}

// ---------------- CSR build --------------------------------------------------
__global__ __launch_bounds__(256) void count_kernel(const int* __restrict__ rows,
                                                    const int* __restrict__ cols) {
    int e = blockIdx.x * blockDim.x + threadIdx.x;
    if (e < EE) {
        atomicAdd(&g_deg[rows[e]], 1);
        atomicAdd(&g_cnt[cols[e]], 1);
    }
}

__global__ __launch_bounds__(256) void scan1_kernel() {
    __shared__ int s[256];
    int tid = threadIdx.x;
    int i = blockIdx.x * 256 + tid;
    s[tid] = (i < NN) ? g_cnt[i] : 0;
    __syncthreads();
    for (int off = 128; off > 0; off >>= 1) {
        if (tid < off) s[tid] += s[tid + off];
        __syncthreads();
    }
    if (tid == 0) g_bsum[blockIdx.x] = s[0];
}

__global__ __launch_bounds__(256) void scan2_kernel() {
    __shared__ int s[256];
    int tid = threadIdx.x;
    s[tid] = (tid < SBLKS) ? g_bsum[tid] : 0;
    __syncthreads();
    for (int off = 1; off < 256; off <<= 1) {
        int v = (tid >= off) ? s[tid - off] : 0;
        __syncthreads();
        s[tid] += v;
        __syncthreads();
    }
    if (tid < SBLKS) g_bpre[tid] = (tid > 0) ? s[tid - 1] : 0;
}

__global__ __launch_bounds__(256) void scan3_kernel() {
    __shared__ int s[256];
    int tid = threadIdx.x;
    int i = blockIdx.x * 256 + tid;
    int c = (i < NN) ? g_cnt[i] : 0;
    s[tid] = c;
    __syncthreads();
    for (int off = 1; off < 256; off <<= 1) {
        int v = (tid >= off) ? s[tid - off] : 0;
        __syncthreads();
        s[tid] += v;
        __syncthreads();
    }
    if (i < NN) {
        int st = g_bpre[blockIdx.x] + s[tid] - c;
        g_startA[i] = st;
        g_cursor[i] = st;
        int d = g_deg[i];
        g_dis[i] = (d > 0) ? rsqrtf((float)d) : 0.f;
    }
}

__global__ __launch_bounds__(256) void scatter_kernel(const int* __restrict__ rows,
                                                      const int* __restrict__ cols) {
    int e = blockIdx.x * blockDim.x + threadIdx.x;
    if (e < EE) {
        int pos = atomicAdd(&g_cursor[cols[e]], 1);
        g_csr_src[pos] = rows[e];
    }
}

// ---------------- gather propagation: out[n] = -dis[n] * sum dis[r]*in[r] ---
// one warp per node; lanes 0..23 each own one float4 chunk of the 96 features.
// pass selects global buffers INSIDE device code (never pass __device__
// symbols as kernel args from host — host shadow address, tripped the guard).
__global__ __launch_bounds__(256) void gather_kernel(int pass) {
    const float* in = (pass == 0) ? g_IN0 : g_OUT1;
    float* out      = (pass == 0) ? g_OUT1 : g_OUT2;
    int gtid = blockIdx.x * blockDim.x + threadIdx.x;
    int n = gtid >> 5;
    int lane = gtid & 31;
    if (n >= NN) return;
    int c = (lane < 24) ? lane : 0;
    float4 acc = make_float4(0.f, 0.f, 0.f, 0.f);
    int s = g_startA[n];
    int e2 = s + g_cnt[n];
#pragma unroll 2
    for (int j = s; j < e2; j++) {
        int r = g_csr_src[j];
        float w = g_dis[r];
        float4 v = ((const float4*)(in + (size_t)r * 96))[c];
        acc.x += w * v.x;
        acc.y += w * v.y;
        acc.z += w * v.z;
        acc.w += w * v.w;
    }
    float dn = -g_dis[n];
    if (lane < 24) {
        float4 o = make_float4(dn * acc.x, dn * acc.y, dn * acc.z, dn * acc.w);
        ((float4*)(out + (size_t)n * 96))[lane] = o;
    }
}

// ---------------- fused gate matmul (K=288) + LSTM update -------------------
// block: 64 nodes x 128 outs, 256 threads: nt=tid&7, ot=tid>>3.
__global__ __launch_bounds__(256) void gates_kernel(const float* __restrict__ wc) {
    __shared__ float sIn[32 * 65];
    __shared__ float sW[32 * 128];
    int tid = threadIdx.x;
    int nt = tid & 7, ot = tid >> 3;
    int nb = blockIdx.x * 64;
    float acc[8][4];
#pragma unroll
    for (int g = 0; g < 4; g++) {
        float b = g_bias[ot + 32 * g];
#pragma unroll
        for (int j = 0; j < 8; j++) acc[j][g] = b;
    }
    for (int cc = 0; cc < 9; cc++) {
        const float* src = (cc < 3) ? g_IN0 : (cc < 6) ? g_OUT1 : g_OUT2;
        int off = (cc - (cc < 3 ? 0 : cc < 6 ? 3 : 6)) * 32;
#pragma unroll
        for (int i = 0; i < 8; i++) {
            int lin = i * 256 + tid;
            int kk = lin & 31, nl = lin >> 5;
            int n = nb + nl;
            sIn[kk * 65 + nl] = (n < NN) ? src[(size_t)n * 96 + off + kk] : 0.f;
        }
        int k0 = cc * 32;
#pragma unroll
        for (int i = 0; i < 16; i++) {
            int lin = i * 256 + tid;
            sW[lin] = g_Wcat[k0 * 128 + lin];
        }
        __syncthreads();
#pragma unroll 4
        for (int kk = 0; kk < 32; kk++) {
            float a[8];
#pragma unroll
            for (int j = 0; j < 8; j++) a[j] = sIn[kk * 65 + nt + 8 * j];
            float w0 = sW[kk * 128 + ot];
            float w1 = sW[kk * 128 + 32 + ot];
            float w2 = sW[kk * 128 + 64 + ot];
            float w3 = sW[kk * 128 + 96 + ot];
#pragma unroll
            for (int j = 0; j < 8; j++) {
                acc[j][0] += a[j] * w0;
                acc[j][1] += a[j] * w1;
                acc[j][2] += a[j] * w2;
                acc[j][3] += a[j] * w3;
            }
        }
        __syncthreads();
    }
    float wci = wc[ot], wcf = wc[32 + ot], wco = wc[64 + ot];
#pragma unroll
    for (int j = 0; j < 8; j++) {
        int n = nb + nt + 8 * j;
        if (n < NN) {
            float cs = g_C[(size_t)n * 32 + ot];
            float ig = sigmoidf_(acc[j][0] + wci * cs);
            float fg = sigmoidf_(acc[j][1] + wcf * cs);
            float gt = tanhf(acc[j][2]);
            float cn = fg * cs + ig * gt;
            float og = sigmoidf_(acc[j][3] + wco * cn);
            g_C[(size_t)n * 32 + ot] = cn;
            g_IN0[(size_t)n * 96 + 64 + ot] = og * tanhf(cn);   // H lives in IN0
        }
    }
}

// ---------------- head: h1 = relu(relu(H) @ fc1 + b1) -----------------------
__global__ __launch_bounds__(256) void h1_kernel(const float* __restrict__ w,
                                                 const float* __restrict__ b) {
    __shared__ float sw[32 * 16];
    __shared__ float sb[16];
    int tid = threadIdx.x;
    for (int i = tid; i < 512; i += blockDim.x) sw[i] = w[i];
    if (tid < 16) sb[tid] = b[tid];
    __syncthreads();
    int n = blockIdx.x * blockDim.x + tid;
    if (n >= NN) return;
    float h[32];
#pragma unroll
    for (int k = 0; k < 32; k++) h[k] = fmaxf(g_IN0[(size_t)n * 96 + 64 + k], 0.f);
#pragma unroll
    for (int o = 0; o < 16; o++) {
        float acc = sb[o];
#pragma unroll
        for (int k = 0; k < 32; k++) acc += h[k] * sw[k * 16 + o];
        g_h1[(size_t)n * 16 + o] = fmaxf(acc, 0.f);
    }
}

// ---------------- head: pair MLP --------------------------------------------
__global__ __launch_bounds__(256) void pair_kernel(
        const int* __restrict__ src, const int* __restrict__ dst,
        const float* __restrict__ w2, const float* __restrict__ b2,
        const float* __restrict__ w3, const float* __restrict__ b3,
        const float* __restrict__ wb, const float* __restrict__ bb,
        float* __restrict__ out) {
    __shared__ float s2[512], s3[128], sb2[16], sb3[8], swb[8];
    __shared__ float sbb;
    int tid = threadIdx.x;
    for (int i = tid; i < 512; i += 256) s2[i] = w2[i];
    for (int i = tid; i < 128; i += 256) s3[i] = w3[i];
    if (tid < 16) sb2[tid] = b2[tid];
    if (tid < 8) { sb3[tid] = b3[tid]; swb[tid] = wb[tid]; }
    if (tid == 0) sbb = bb[0];
    __syncthreads();
    int p = blockIdx.x * 256 + tid;
    if (p >= PP) return;
    int s = src[p], d = dst[p];
    float z[32];
    const float4* hs = (const float4*)(g_h1 + (size_t)s * 16);
    const float4* hd = (const float4*)(g_h1 + (size_t)d * 16);
#pragma unroll
    for (int q = 0; q < 4; q++) {
        float4 v = hs[q];
        z[q * 4 + 0] = v.x; z[q * 4 + 1] = v.y; z[q * 4 + 2] = v.z; z[q * 4 + 3] = v.w;
    }
#pragma unroll
    for (int q = 0; q < 4; q++) {
        float4 v = hd[q];
        z[16 + q * 4 + 0] = v.x; z[16 + q * 4 + 1] = v.y; z[16 + q * 4 + 2] = v.z; z[16 + q * 4 + 3] = v.w;
    }
    float h2[16];
#pragma unroll
    for (int o = 0; o < 16; o++) {
        float acc = sb2[o];
#pragma unroll
        for (int k = 0; k < 32; k++) acc += z[k] * s2[k * 16 + o];
        h2[o] = fmaxf(acc, 0.f);
    }
    float h3[8];
#pragma unroll
    for (int o = 0; o < 8; o++) {
        float acc = sb3[o];
#pragma unroll
        for (int k = 0; k < 16; k++) acc += h2[k] * s3[k * 8 + o];
        h3[o] = fmaxf(acc, 0.f);
    }
    float acc = sbb;
#pragma unroll
    for (int k = 0; k < 8; k++) acc += h3[k] * swb[k];
    out[p] = sigmoidf_(acc);
}

// ---------------- launch ----------------------------------------------------
extern "C" void kernel_launch(void* const* d_in, const int* in_sizes, int n_in,
                              void* d_out, int out_size) {
    const float* x    = (const float*)d_in[0];
    const int*   ei   = (const int*)d_in[1];
    const int*   src  = (const int*)d_in[2];
    const int*   dst  = (const int*)d_in[3];
    const float* Wx   = (const float*)d_in[4];
    const float* bx   = (const float*)d_in[5];
    const float* Wh   = (const float*)d_in[6];
    const float* bh   = (const float*)d_in[7];
    const float* bg   = (const float*)d_in[8];
    const float* wc   = (const float*)d_in[9];
    const float* fc1w = (const float*)d_in[10];
    const float* fc1b = (const float*)d_in[11];
    const float* fc2w = (const float*)d_in[12];
    const float* fc2b = (const float*)d_in[13];
    const float* fc3w = (const float*)d_in[14];
    const float* fc3b = (const float*)d_in[15];
    const float* bfcw = (const float*)d_in[16];
    const float* bfcb = (const float*)d_in[17];
    float* out = (float*)d_out;

    prep_weights<<<64, 256>>>(Wx, bx, Wh, bh, bg);
    copyx_kernel<<<512, 256>>>(x);
    zero_state<<<512, 256>>>();

    for (int t = 0; t < TT; t++) {
        const int* rows = ei + (size_t)t * 2 * EE;
        const int* cols = rows + EE;
        zero_counts<<<SBLKS, 256>>>();
        count_kernel<<<(EE + 255) / 256, 256>>>(rows, cols);
        scan1_kernel<<<SBLKS, 256>>>();
        scan2_kernel<<<1, 256>>>();
        scan3_kernel<<<SBLKS, 256>>>();
        scatter_kernel<<<(EE + 255) / 256, 256>>>(rows, cols);
        gather_kernel<<<(NN * 32 + 255) / 256, 256>>>(0);
        gather_kernel<<<(NN * 32 + 255) / 256, 256>>>(1);
        gates_kernel<<<(NN + 63) / 64, 256>>>(wc);
    }

    h1_kernel<<<(NN + 255) / 256, 256>>>(fc1w, fc1b);
    pair_kernel<<<(PP + 255) / 256, 256>>>(src, dst, fc2w, fc2b, fc3w, fc3b, bfcw, bfcb, out);
}